// round 4
// baseline (speedup 1.0000x reference)
#include <cuda_runtime.h>
#include <cstdint>

// Problem constants (fixed for MaskPS_31774168056092)
#define BB 2
#define PP 200000
#define QQ 100
#define NEG_BIG (-1e30f)

// Scratch (no allocations allowed): per-query tables.
__device__ float2 g_sb[BB][QQ];       // (score, bias) bias = 0 if kept else -1e30
__device__ int    g_nonempty[BB][QQ];
__device__ int    g_seg[BB][QQ];

// Fast, flag-independent reciprocal: rcp.approx + 1 Newton (~0.5-1 ulp).
__device__ __forceinline__ float fast_rcp(float d) {
    float r;
    asm("rcp.approx.f32 %0, %1;" : "=f"(r) : "f"(d));
    // r = r + r*(1 - d*r)
    r = fmaf(fmaf(-d, r, 1.0f), r, r);
    return r;
}

// ---------------------------------------------------------------------------
// Kernel 1: per-query prep. scores = max(l0,l1); keep = !(l1 > l0) (argmax
// first-tie -> label 0). bias kills non-kept queries in the masked argmax.
// Also zeroes the nonempty flags (graph replays must be deterministic).
// ---------------------------------------------------------------------------
__global__ void prep_kernel(const float* __restrict__ logits) {
    int t = threadIdx.x;
    if (t < BB * QQ) {
        int b = t / QQ, q = t % QQ;
        float l0 = logits[(b * QQ + q) * 2 + 0];
        float l1 = logits[(b * QQ + q) * 2 + 1];
        float s = fmaxf(l0, l1);
        bool keep = !(l1 > l0);
        g_sb[b][q] = make_float2(s, keep ? 0.0f : NEG_BIG);
        g_nonempty[b][q] = 0;
    }
}

// ---------------------------------------------------------------------------
// Kernel 2: main per-point kernel. One thread per point.
//  sweep 1: v[j] = s_j * sigmoid(x_j) + bias_j  (accurate), M = max_j v[j]
//  sweep 2: mid = first argmax, S = sum_j exp(v[j]-M)
//  outputs: sem=0, ins_tmp = valid ? mid+1 : 0, max_conf = 1/S
//  nonempty flags via smem OR -> one atomicOr per query per CTA.
// ---------------------------------------------------------------------------
__global__ void __launch_bounds__(128, 1) main_kernel(
    const float* __restrict__ masks,
    const unsigned char* __restrict__ pad,
    float* __restrict__ out)
{
    __shared__ float2 sb[QQ];
    __shared__ int flags[QQ];
    const int tid = threadIdx.x;
    const int b = blockIdx.y;
    if (tid < QQ) { sb[tid] = g_sb[b][tid]; flags[tid] = 0; }
    __syncthreads();

    const int p = blockIdx.x * blockDim.x + tid;
    const bool active = (p < PP);
    const int pc = active ? p : (PP - 1);

    const float4* row =
        reinterpret_cast<const float4*>(masks + ((size_t)b * PP + pc) * QQ);

    float v[QQ];
    float M = -3.4e38f;

    #pragma unroll
    for (int j4 = 0; j4 < QQ / 4; j4++) {
        float4 x4 = __ldg(&row[j4]);
        float xs0 = x4.x, xs1 = x4.y, xs2 = x4.z, xs3 = x4.w;
        #pragma unroll
        for (int k = 0; k < 4; k++) {
            int j = j4 * 4 + k;
            float x = (k == 0) ? xs0 : (k == 1) ? xs1 : (k == 2) ? xs2 : xs3;
            float2 s = sb[j];
            float e = __expf(-fabsf(x));          // FMUL + MUFU.EX2
            float num = (x < 0.0f) ? e : 1.0f;
            float sig = num * fast_rcp(1.0f + e); // sigmoid, ~1-2 ulp
            float vj = fmaf(s.x, sig, s.y);       // single rounding like ref
            v[j] = vj;
            M = fmaxf(M, vj);
        }
    }

    // Sweep 2: argmax index (first max) + softmax normalizer.
    float S0 = 0.0f, S1 = 0.0f, S2 = 0.0f, S3 = 0.0f;
    int mid = QQ - 1;
    #pragma unroll
    for (int j = QQ - 1; j >= 0; j--) {
        mid = (v[j] == M) ? j : mid;   // descending scan -> first (smallest) idx
    }
    #pragma unroll
    for (int j = 0; j < QQ; j += 4) {
        S0 += __expf(v[j + 0] - M);
        S1 += __expf(v[j + 1] - M);
        S2 += __expf(v[j + 2] - M);
        S3 += __expf(v[j + 3] - M);
    }
    float S = (S0 + S1) + (S2 + S3);

    // Recover sigmoid at mid: v_mid = s*sig (+0 bias when kept) -> sig = M/s.
    float2 sm = sb[mid];
    float sig_mid = M * fast_rcp(sm.x);
    // refine to near-RN: one more Newton already inside fast_rcp; good to ~1ulp
    bool keepm = (sm.y == 0.0f);
    bool validp = active && keepm && (sig_mid >= 1e-3f) &&
                  (pad[(size_t)b * PP + pc] == 0);

    if (validp) flags[mid] = 1;   // benign race: same value

    if (active) {
        size_t base = (size_t)b * PP + p;
        out[base] = 0.0f;                                            // sem == 0
        out[(size_t)BB * PP + base] = validp ? (float)(mid + 1) : 0.0f; // tmp
        out[(size_t)2 * BB * PP + base] = fast_rcp(S);               // max_conf
    }

    __syncthreads();
    if (tid < QQ && flags[tid]) atomicOr(&g_nonempty[b][tid], 1);
}

// ---------------------------------------------------------------------------
// Kernel 3: 100-entry cumsum of nonempty -> segment ids (per batch).
// ---------------------------------------------------------------------------
__global__ void seg_kernel() {
    int b = threadIdx.x;
    if (b < BB) {
        int run = 0;
        for (int q = 0; q < QQ; q++) {
            run += (g_nonempty[b][q] != 0) ? 1 : 0;
            g_seg[b][q] = run;
        }
    }
}

// ---------------------------------------------------------------------------
// Kernel 4: remap ins tmp (mid+1) -> seg_id[mid].
// ---------------------------------------------------------------------------
__global__ void remap_kernel(float* __restrict__ out) {
    int i = blockIdx.x * blockDim.x + threadIdx.x;
    if (i < BB * PP) {
        float t = out[(size_t)BB * PP + i];
        if (t != 0.0f) {
            int b = i / PP;
            int q = (int)t - 1;
            out[(size_t)BB * PP + i] = (float)g_seg[b][q];
        }
    }
}

extern "C" void kernel_launch(void* const* d_in, const int* in_sizes, int n_in,
                              void* d_out, int out_size) {
    const float* logits = (const float*)d_in[0];
    const float* masks  = (const float*)d_in[1];
    const unsigned char* pad = (const unsigned char*)d_in[2];
    float* out = (float*)d_out;

    prep_kernel<<<1, 256>>>(logits);

    dim3 grid((PP + 127) / 128, BB);
    main_kernel<<<grid, 128>>>(masks, pad, out);

    seg_kernel<<<1, 32>>>();

    remap_kernel<<<(BB * PP + 255) / 256, 256>>>(out);
}